// round 9
// baseline (speedup 1.0000x reference)
#include <cuda_runtime.h>
#include <float.h>

#define N 16384
#define H 64
#define EPSF 1e-8f
#define GRID 128
#define TPB 128
#define NB 65536      // buckets = top 16 bits of order-preserving key
#define NCOARSE 128   // 512 buckets per coarse bin == one block's bucket range

// ---------------- scratch (device globals; no allocation allowed) ------------
// 64-bit slots: (tag<<32)|key. tag unique per execution -> no zeroing needed.
__device__ unsigned long long g_tmp64[N];     // scattered, tag-protected
__device__ unsigned long long g_sorted64[N];  // sorted, tag-protected
__device__ int   g_cnt[NB];        // INVARIANT: zero at entry; re-zeroed phase 2
__device__ int   g_off[NB];        // scatter counters; fully rewritten each run
__device__ int   g_start[NB + 4];  // pristine starts; [NB] = N
__device__ int   g_coarse[NCOARSE];// INVARIANT: zero at entry; re-zeroed phase 2
__device__ float g_pmse[GRID], g_pd2[GRID], g_pdens[GRID], g_pdmax[GRID];
__device__ unsigned g_arrive = 0;  // barrier arrival counter (self-resetting)
__device__ unsigned g_epoch  = 0;  // barrier epoch (monotonic, wrap-safe)
__device__ unsigned g_done   = 0;  // finalize counter (self-resetting)

// ---------------- helpers -----------------------------------------------------
__device__ __forceinline__ float warp_sum(float v) {
#pragma unroll
    for (int o = 16; o > 0; o >>= 1) v += __shfl_xor_sync(0xffffffffu, v, o);
    return v;
}
__device__ __forceinline__ float warp_max(float v) {
#pragma unroll
    for (int o = 16; o > 0; o >>= 1) v = fmaxf(v, __shfl_xor_sync(0xffffffffu, v, o));
    return v;
}
__device__ __forceinline__ int warp_sumi(int v) {
#pragma unroll
    for (int o = 16; o > 0; o >>= 1) v += __shfl_xor_sync(0xffffffffu, v, o);
    return v;
}
__device__ __forceinline__ unsigned int okey(float f) {
    unsigned int u = __float_as_uint(f);
    return (u & 0x80000000u) ? ~u : (u | 0x80000000u);
}
__device__ __forceinline__ float inv_okey(unsigned k) {
    unsigned u = (k & 0x80000000u) ? (k ^ 0x80000000u) : ~k;
    return __uint_as_float(u);
}

// grid-wide flat barrier (round-7 proven): all GRID blocks co-resident.
// __threadfence orders writes into L2 AND emits CCTL.IVALL (own-L1 invalidate).
__device__ __forceinline__ void grid_sync(unsigned base, unsigned ph) {
    __syncthreads();
    if (threadIdx.x == 0) {
        __threadfence();
        unsigned a = atomicAdd(&g_arrive, 1);
        if (a == GRID - 1) {
            atomicExch(&g_arrive, 0);
            __threadfence();
            atomicAdd(&g_epoch, 1);     // release
        } else {
            while ((*(volatile unsigned*)&g_epoch) - base < ph) { }
        }
    }
    __syncthreads();
}

__global__ void __launch_bounds__(TPB, 1)
fused_kernel(const float* __restrict__ x,   const float* __restrict__ tgt,
             const float* __restrict__ w1,  const float* __restrict__ b1,
             const float* __restrict__ w2,  const float* __restrict__ b2,
             float* __restrict__ out) {
    __shared__ float sw1x2[H], sb1x2[H], sw2[H], sc2[H];
    __shared__ float sA[4], sB[4];
    __shared__ int   sI[4];
    __shared__ int   scoarse[NCOARSE];
    __shared__ unsigned s_base;
    __shared__ int   s_final;

    const int tid = threadIdx.x;
    const int blk = blockIdx.x;
    const int gi  = blk * TPB + tid;
    const int lane = tid & 31, wid = tid >> 5;

    if (tid == 0) s_base = *(volatile unsigned*)&g_epoch;  // pre-barrier, uniform

    if (tid < H) {
        float a = w1[tid];
        float c = w2[tid];
        sw1x2[tid] = a + a;            // fold x2 of exp(2u) into weights
        sb1x2[tid] = 2.0f * b1[tid];
        sw2[tid] = c;
        sc2[tid] = -2.0f * c * a * a;  // coeff of t*(1-t^2) in d2y/dx2
    }
    scoarse[tid] = 0;
    __syncthreads();
    const unsigned base = s_base;
    const unsigned tag  = base + 1;    // unique per execution (epoch += 2 per run)

    // ---------------- phase 0: MLP partials + fine/coarse histogram -------------
    const float xv = x[gi];
    float pred = b2[0];
    float d2 = 0.0f;
#pragma unroll
    for (int h = 0; h < H; ++h) {
        float u2 = fmaf(xv, sw1x2[h], sb1x2[h]);
        float e  = __expf(u2);
        float t  = 1.0f - __fdividef(2.0f, e + 1.0f);     // tanh(u)
        pred = fmaf(sw2[h], t, pred);
        float t2 = t * t;
        float g  = fmaf(-t2, t, t);                       // t - t^3
        d2 = fmaf(sc2[h], g, d2);
    }
    {
        float err = pred - tgt[gi];
        float vm = warp_sum(err * err);
        float vd = warp_sum(d2 * d2);
        if (lane == 0) { sA[wid] = vm; sB[wid] = vd; }
        __syncthreads();
        if (tid == 0) {
            g_pmse[blk] = sA[0] + sA[1] + sA[2] + sA[3];
            g_pd2[blk]  = sB[0] + sB[1] + sB[2] + sB[3];
        }
    }
    const unsigned key = okey(xv);
    const unsigned b = key >> 16;
    atomicAdd(&g_cnt[b], 1);            // fine (spread addresses)
    atomicAdd(&scoarse[b >> 9], 1);     // coarse in smem (cheap ATOMS)
    __syncthreads();
    if (scoarse[tid]) atomicAdd(&g_coarse[tid], scoarse[tid]);  // 128 adds/addr max

    grid_sync(base, 1);

    // ---------------- phase 1: scan + absolute offsets (no totals barrier) ------
    int4 c4 = reinterpret_cast<const int4*>(g_cnt)[gi];
    int s = c4.x + c4.y + c4.z + c4.w;
    int inc = s;
#pragma unroll
    for (int o = 1; o < 32; o <<= 1) {
        int nb = __shfl_up_sync(0xffffffffu, inc, o);
        if (lane >= o) inc += nb;
    }
    if (lane == 31) sI[wid] = inc;
    __syncthreads();
    if (wid == 0 && lane < 4) {
        int v = sI[lane];
        int wi = v;
#pragma unroll
        for (int o = 1; o < 4; o <<= 1) {
            int nb = __shfl_up_sync(0x0000000fu, wi, o);
            if (lane >= o) wi += nb;
        }
        sI[lane] = wi - v;
    }
    __syncthreads();
    int e_blk = sI[wid] + (inc - s);     // block-local exclusive base
    __syncthreads();                     // sI reuse boundary
    {
        int pv = (tid < blk) ? g_coarse[tid] : 0;  // coarse bin j == block j's range
        pv = warp_sumi(pv);
        if (lane == 0) sI[wid] = pv;
        __syncthreads();
        int bbase = sI[0] + sI[1] + sI[2] + sI[3];
        int e_abs = bbase + e_blk;
        int4 o4;
        o4.x = e_abs;
        o4.y = o4.x + c4.x;
        o4.z = o4.y + c4.y;
        o4.w = o4.z + c4.z;
        reinterpret_cast<int4*>(g_off)[gi] = o4;
        reinterpret_cast<int4*>(g_start)[gi] = o4;
        if (blk == GRID - 1 && tid == TPB - 1) g_start[NB] = e_abs + s;  // = N
    }

    grid_sync(base, 2);

    // ---------------- phase 2: scatter + rank + density (tag-protocol fused) ----
    // restore invariants (all reads of g_cnt/g_coarse ended before B2)
    reinterpret_cast<int4*>(g_cnt)[gi] = make_int4(0, 0, 0, 0);
    if (blk == 0) g_coarse[tid] = 0;

    // scatter
    const int pos = atomicAdd(&g_off[b], 1);
    const unsigned long long myslot = ((unsigned long long)tag << 32) | (unsigned long long)key;
    *(volatile unsigned long long*)&g_tmp64[pos] = myslot;

    // rank: spin-scan own segment, 8 independent polls per round (pipelined)
    const int st = g_start[b];
    const int en = g_start[b + 1];
    int r = 0;
    for (int q0 = st; q0 < en; q0 += 8) {
        int m = en - q0; if (m > 8) m = 8;
        unsigned kq[8];
        unsigned dm = 0;
        const unsigned full = (1u << m) - 1u;
        while (dm != full) {
#pragma unroll
            for (int j = 0; j < 8; ++j) {
                if (j < m && !(dm & (1u << j))) {
                    unsigned long long w = *(volatile const unsigned long long*)&g_tmp64[q0 + j];
                    if ((unsigned)(w >> 32) == tag) { kq[j] = (unsigned)w; dm |= (1u << j); }
                }
            }
        }
#pragma unroll
        for (int j = 0; j < 8; ++j)
            if (j < m) r += (kq[j] < key) || (kq[j] == key && (q0 + j) < pos);
    }
    const int p = st + r;
    *(volatile unsigned long long*)&g_sorted64[p] = myslot;

    // density at own sorted position p: spin-read +-2 neighbors (independent polls)
    {
        unsigned nk0 = 0, nk1 = 0, nk2 = 0, nk3 = 0;
        unsigned need = 0, got = 0;
        if (p >= 2)     need |= 1u;
        if (p >= 1)     need |= 2u;
        if (p + 1 < N)  need |= 4u;
        if (p + 2 < N)  need |= 8u;
        while (got != need) {
            if ((need & 1u) && !(got & 1u)) {
                unsigned long long w = *(volatile const unsigned long long*)&g_sorted64[p - 2];
                if ((unsigned)(w >> 32) == tag) { nk0 = (unsigned)w; got |= 1u; }
            }
            if ((need & 2u) && !(got & 2u)) {
                unsigned long long w = *(volatile const unsigned long long*)&g_sorted64[p - 1];
                if ((unsigned)(w >> 32) == tag) { nk1 = (unsigned)w; got |= 2u; }
            }
            if ((need & 4u) && !(got & 4u)) {
                unsigned long long w = *(volatile const unsigned long long*)&g_sorted64[p + 1];
                if ((unsigned)(w >> 32) == tag) { nk2 = (unsigned)w; got |= 4u; }
            }
            if ((need & 8u) && !(got & 8u)) {
                unsigned long long w = *(volatile const unsigned long long*)&g_sorted64[p + 2];
                if ((unsigned)(w >> 32) == tag) { nk3 = (unsigned)w; got |= 8u; }
            }
        }
        float xi = xv;
        float c1 = (need & 1u) ? xi - inv_okey(nk0) : FLT_MAX;  // gap to pred2
        float c0 = (need & 2u) ? xi - inv_okey(nk1) : FLT_MAX;  // gap to pred1
        float c2 = (need & 4u) ? inv_okey(nk2) - xi : FLT_MAX;  // gap to succ1
        float c3 = (need & 8u) ? inv_okey(nk3) - xi : FLT_MAX;  // gap to succ2
        float m1 = fminf(c0, c2);
        float m2 = (c0 < c2) ? fminf(c1, c2) : fminf(c0, c3);
        float knn_mean = (m1 + m2 + 3.0f * EPSF) * (1.0f / 3.0f);
        float dens = 1.0f / (knn_mean + EPSF);

        float vs = warp_sum(dens);
        float vx = warp_max(dens);
        if (lane == 0) { sA[wid] = vs; sB[wid] = vx; }
        __syncthreads();
        if (tid == 0) {
            g_pdens[blk] = sA[0] + sA[1] + sA[2] + sA[3];
            g_pdmax[blk] = fmaxf(fmaxf(sB[0], sB[1]), fmaxf(sB[2], sB[3]));
        }
    }

    // ---------------- phase 3: last-arriving block finalizes ---------------------
    if (tid == 0) {
        __threadfence();                      // push partials to L2 + IVALL own L1
        unsigned old = atomicAdd(&g_done, 1);
        s_final = (old == GRID - 1);
        if (s_final) atomicExch(&g_done, 0);  // reset invariant
    }
    __syncthreads();
    if (s_final) {
        float vm = __ldcg(&g_pmse[tid]);
        float vd = __ldcg(&g_pd2[tid]);
        float vs = __ldcg(&g_pdens[tid]);
        float vx = __ldcg(&g_pdmax[tid]);
        vm = warp_sum(vm);
        vd = warp_sum(vd);
        vs = warp_sum(vs);
        vx = warp_max(vx);
        if (lane == 0) { sA[wid] = vm; sB[wid] = vd; sw1x2[wid] = vs; sw2[wid] = vx; }
        __syncthreads();
        if (tid == 0) {
            float mse  = (sA[0] + sA[1] + sA[2] + sA[3]) * (1.0f / N);
            float md2  = (sB[0] + sB[1] + sB[2] + sB[3]) * (1.0f / N);
            float dsum = (sw1x2[0] + sw1x2[1] + sw1x2[2] + sw1x2[3]);
            float dmax = fmaxf(fmaxf(sw2[0], sw2[1]), fmaxf(sw2[2], sw2[3]));
            float mean_dnorm = (dsum * (1.0f / N)) / (dmax + EPSF);
            float mean_w = 1.0f + 0.1f * mean_dnorm;
            float penalty = 0.01f * mean_w * md2;
            out[0] = mse + penalty;
            out[1] = mse;
            out[2] = penalty;
        }
    }
}

// ---------------- launch ----------------------------------------------------------
extern "C" void kernel_launch(void* const* d_in, const int* in_sizes, int n_in,
                              void* d_out, int out_size) {
    const float* x   = (const float*)d_in[0];
    const float* tgt = (const float*)d_in[1];
    const float* w1  = (const float*)d_in[2];
    const float* b1  = (const float*)d_in[3];
    const float* w2  = (const float*)d_in[4];
    const float* b2  = (const float*)d_in[5];
    float* out = (float*)d_out;

    fused_kernel<<<GRID, TPB>>>(x, tgt, w1, b1, w2, b2, out);
    (void)in_sizes; (void)n_in; (void)out_size;
}

// round 10
// speedup vs baseline: 1.4987x; 1.4987x over previous
#include <cuda_runtime.h>
#include <float.h>

#define N 16384
#define H 64
#define EPSF 1e-8f
#define GRID 128
#define TPB 128
#define NB 65536      // buckets = top 16 bits of order-preserving key
#define NCOARSE 128   // 512 buckets per coarse bin == one block's bucket range

// ---------------- scratch (device globals; no allocation allowed) ------------
__device__ __align__(16) float g_tmp[N];          // bucket-grouped values
__device__ __align__(16) int   g_cnt[NB];         // INVARIANT: zero at entry; re-zeroed phase 2
__device__ __align__(16) int   g_start[NB + 4];   // bucket starts (prefix); [NB] = N
__device__ __align__(16) int   g_coarse[NCOARSE]; // INVARIANT: zero at entry; re-zeroed phase 2
__device__ float g_pmse[GRID], g_pd2[GRID], g_pdens[GRID], g_pdmax[GRID];
__device__ unsigned g_arrive = 0;  // barrier arrival counter (self-resetting)
__device__ unsigned g_epoch  = 0;  // barrier epoch (monotonic, wrap-safe)
__device__ unsigned g_done   = 0;  // finalize counter (self-resetting)

// ---------------- helpers -----------------------------------------------------
__device__ __forceinline__ float warp_sum(float v) {
#pragma unroll
    for (int o = 16; o > 0; o >>= 1) v += __shfl_xor_sync(0xffffffffu, v, o);
    return v;
}
__device__ __forceinline__ float warp_max(float v) {
#pragma unroll
    for (int o = 16; o > 0; o >>= 1) v = fmaxf(v, __shfl_xor_sync(0xffffffffu, v, o));
    return v;
}
__device__ __forceinline__ int warp_sumi(int v) {
#pragma unroll
    for (int o = 16; o > 0; o >>= 1) v += __shfl_xor_sync(0xffffffffu, v, o);
    return v;
}
__device__ __forceinline__ unsigned int okey(float f) {
    unsigned int u = __float_as_uint(f);
    return (u & 0x80000000u) ? ~u : (u | 0x80000000u);
}
__device__ __forceinline__ float inv_okey(unsigned k) {
    unsigned u = (k & 0x80000000u) ? (k ^ 0x80000000u) : ~k;
    return __uint_as_float(u);
}

// grid-wide flat barrier (round-7 proven): all GRID blocks co-resident.
// __threadfence orders writes into L2 AND emits CCTL.IVALL (own-L1 invalidate),
// so post-barrier plain loads refetch fresh data from L2.
__device__ __forceinline__ void grid_sync(unsigned base, unsigned ph) {
    __syncthreads();
    if (threadIdx.x == 0) {
        __threadfence();
        unsigned a = atomicAdd(&g_arrive, 1);
        if (a == GRID - 1) {
            atomicExch(&g_arrive, 0);
            __threadfence();
            atomicAdd(&g_epoch, 1);     // release
        } else {
            while ((*(volatile unsigned*)&g_epoch) - base < ph) { }
        }
    }
    __syncthreads();
}

__global__ void __launch_bounds__(TPB, 1)
fused_kernel(const float* __restrict__ x,   const float* __restrict__ tgt,
             const float* __restrict__ w1,  const float* __restrict__ b1,
             const float* __restrict__ w2,  const float* __restrict__ b2,
             float* __restrict__ out) {
    __shared__ float sw1x2[H], sb1x2[H], sw2[H], sc2[H];
    __shared__ float sA[4], sB[4];
    __shared__ int   sI[4];
    __shared__ int   scoarse[NCOARSE];
    __shared__ unsigned s_base;
    __shared__ int   s_final;

    const int tid = threadIdx.x;
    const int blk = blockIdx.x;
    const int gi  = blk * TPB + tid;
    const int lane = tid & 31, wid = tid >> 5;

    if (tid == 0) s_base = *(volatile unsigned*)&g_epoch;  // pre-barrier, uniform

    if (tid < H) {
        float a = w1[tid];
        float c = w2[tid];
        sw1x2[tid] = a + a;            // fold x2 of exp(2u) into weights
        sb1x2[tid] = 2.0f * b1[tid];
        sw2[tid] = c;
        sc2[tid] = -2.0f * c * a * a;  // coeff of t*(1-t^2) in d2y/dx2
    }
    scoarse[tid] = 0;
    __syncthreads();
    const unsigned base = s_base;

    // ---------------- phase 0: MLP partials + fine/coarse histogram -------------
    const float xv = x[gi];
    float pred = b2[0];
    float d2 = 0.0f;
#pragma unroll
    for (int h = 0; h < H; ++h) {
        float u2 = fmaf(xv, sw1x2[h], sb1x2[h]);
        float e  = __expf(u2);
        float t  = 1.0f - __fdividef(2.0f, e + 1.0f);     // tanh(u)
        pred = fmaf(sw2[h], t, pred);
        float t2 = t * t;
        float g  = fmaf(-t2, t, t);                       // t - t^3
        d2 = fmaf(sc2[h], g, d2);
    }
    {
        float err = pred - tgt[gi];
        float vm = warp_sum(err * err);
        float vd = warp_sum(d2 * d2);
        if (lane == 0) { sA[wid] = vm; sB[wid] = vd; }
        __syncthreads();
        if (tid == 0) {
            g_pmse[blk] = sA[0] + sA[1] + sA[2] + sA[3];
            g_pd2[blk]  = sB[0] + sB[1] + sB[2] + sB[3];
        }
    }
    const unsigned b = okey(xv) >> 16;
    const int r_i = atomicAdd(&g_cnt[b], 1);   // within-bucket index (free!)
    atomicAdd(&scoarse[b >> 9], 1);            // coarse histogram in smem
    __syncthreads();
    if (scoarse[tid]) atomicAdd(&g_coarse[tid], scoarse[tid]);

    grid_sync(base, 1);

    // ---------------- phase 1: scan + absolute bucket starts --------------------
    int4 c4 = reinterpret_cast<const int4*>(g_cnt)[gi];
    int s = c4.x + c4.y + c4.z + c4.w;
    int inc = s;
#pragma unroll
    for (int o = 1; o < 32; o <<= 1) {
        int nb = __shfl_up_sync(0xffffffffu, inc, o);
        if (lane >= o) inc += nb;
    }
    if (lane == 31) sI[wid] = inc;
    __syncthreads();
    if (wid == 0 && lane < 4) {
        int v = sI[lane];
        int wi = v;
#pragma unroll
        for (int o = 1; o < 4; o <<= 1) {
            int nb = __shfl_up_sync(0x0000000fu, wi, o);
            if (lane >= o) wi += nb;
        }
        sI[lane] = wi - v;
    }
    __syncthreads();
    int e_blk = sI[wid] + (inc - s);     // block-local exclusive base
    __syncthreads();                     // sI reuse boundary
    {
        int pv = (tid < blk) ? g_coarse[tid] : 0;  // coarse bin j == block j's range
        pv = warp_sumi(pv);
        if (lane == 0) sI[wid] = pv;
        __syncthreads();
        int bbase = sI[0] + sI[1] + sI[2] + sI[3];
        int e_abs = bbase + e_blk;
        int4 o4;
        o4.x = e_abs;
        o4.y = o4.x + c4.x;
        o4.z = o4.y + c4.y;
        o4.w = o4.z + c4.z;
        reinterpret_cast<int4*>(g_start)[gi] = o4;
        if (blk == GRID - 1 && tid == TPB - 1) g_start[NB] = e_abs + s;  // = N
    }

    grid_sync(base, 2);

    // ---------------- phase 2: scatter (no atomics) + restore invariants --------
    reinterpret_cast<int4*>(g_cnt)[gi] = make_int4(0, 0, 0, 0);
    if (blk == 0) g_coarse[tid] = 0;
    const int st  = g_start[b];
    const int pos = st + r_i;
    g_tmp[pos] = xv;

    grid_sync(base, 3);

    // ---------------- phase 3: two smallest gaps via bucket walk -----------------
    {
        const int en = g_start[b + 1];
        float g1 = FLT_MAX, g2 = FLT_MAX;
        // own bucket (skip self; duplicates elsewhere give gap 0, matching ref)
        for (int q = st; q < en; ++q) {
            if (q == pos) continue;
            float g = fabsf(g_tmp[q] - xv);
            if (g < g1) { g2 = g1; g1 = g; } else if (g < g2) { g2 = g; }
        }
        // left walk: hop to previous NONEMPTY bucket in O(1) via element at st-1
        int lpos = st - 1;
        while (lpos >= 0) {
            float v = g_tmp[lpos];
            unsigned c = okey(v) >> 16;
            // conservative stop: even the largest possible value in bucket c
            // is >= g2 away -> nothing in c or further left can improve
            float ub = inv_okey((c << 16) | 0xFFFFu);
            if (xv - ub >= g2) break;
            int cst = g_start[c];
            for (int q = cst; q <= lpos; ++q) {
                float g = xv - g_tmp[q];        // strictly lower bucket -> positive
                if (g < g1) { g2 = g1; g1 = g; } else if (g < g2) { g2 = g; }
            }
            lpos = cst - 1;
        }
        // right walk (symmetric)
        int rpos = en;
        while (rpos < N) {
            float v = g_tmp[rpos];
            unsigned c = okey(v) >> 16;
            float lb = inv_okey(c << 16);
            if (lb - xv >= g2) break;
            int cen = g_start[c + 1];
            for (int q = rpos; q < cen; ++q) {
                float g = g_tmp[q] - xv;
                if (g < g1) { g2 = g1; g1 = g; } else if (g < g2) { g2 = g; }
            }
            rpos = cen;
        }
        // knn vals = {EPS, g1+EPS, g2+EPS}
        float knn_mean = (g1 + g2 + 3.0f * EPSF) * (1.0f / 3.0f);
        float dens = 1.0f / (knn_mean + EPSF);

        float vs = warp_sum(dens);
        float vx = warp_max(dens);
        if (lane == 0) { sA[wid] = vs; sB[wid] = vx; }
        __syncthreads();
        if (tid == 0) {
            g_pdens[blk] = sA[0] + sA[1] + sA[2] + sA[3];
            g_pdmax[blk] = fmaxf(fmaxf(sB[0], sB[1]), fmaxf(sB[2], sB[3]));
        }
    }

    // ---------------- phase 4: last-arriving block finalizes ---------------------
    if (tid == 0) {
        __threadfence();                      // push partials to L2 + IVALL own L1
        unsigned old = atomicAdd(&g_done, 1);
        s_final = (old == GRID - 1);
        if (s_final) atomicExch(&g_done, 0);  // reset invariant
    }
    __syncthreads();
    if (s_final) {
        float vm = __ldcg(&g_pmse[tid]);
        float vd = __ldcg(&g_pd2[tid]);
        float vs = __ldcg(&g_pdens[tid]);
        float vx = __ldcg(&g_pdmax[tid]);
        vm = warp_sum(vm);
        vd = warp_sum(vd);
        vs = warp_sum(vs);
        vx = warp_max(vx);
        if (lane == 0) { sA[wid] = vm; sB[wid] = vd; sw1x2[wid] = vs; sw2[wid] = vx; }
        __syncthreads();
        if (tid == 0) {
            float mse  = (sA[0] + sA[1] + sA[2] + sA[3]) * (1.0f / N);
            float md2  = (sB[0] + sB[1] + sB[2] + sB[3]) * (1.0f / N);
            float dsum = (sw1x2[0] + sw1x2[1] + sw1x2[2] + sw1x2[3]);
            float dmax = fmaxf(fmaxf(sw2[0], sw2[1]), fmaxf(sw2[2], sw2[3]));
            float mean_dnorm = (dsum * (1.0f / N)) / (dmax + EPSF);
            float mean_w = 1.0f + 0.1f * mean_dnorm;
            float penalty = 0.01f * mean_w * md2;
            out[0] = mse + penalty;
            out[1] = mse;
            out[2] = penalty;
        }
    }
}

// ---------------- launch ----------------------------------------------------------
extern "C" void kernel_launch(void* const* d_in, const int* in_sizes, int n_in,
                              void* d_out, int out_size) {
    const float* x   = (const float*)d_in[0];
    const float* tgt = (const float*)d_in[1];
    const float* w1  = (const float*)d_in[2];
    const float* b1  = (const float*)d_in[3];
    const float* w2  = (const float*)d_in[4];
    const float* b2  = (const float*)d_in[5];
    float* out = (float*)d_out;

    fused_kernel<<<GRID, TPB>>>(x, tgt, w1, b1, w2, b2, out);
    (void)in_sizes; (void)n_in; (void)out_size;
}

// round 11
// speedup vs baseline: 1.8740x; 1.2504x over previous
#include <cuda_runtime.h>
#include <float.h>

#define N 16384
#define H 64
#define EPSF 1e-8f
#define GRID 64
#define TPB 256
#define NW (TPB / 32)      // 8 warps
#define NB 65536           // buckets = top 16 bits of order-preserving key
#define NCOARSE 64         // 1024 buckets per coarse bin == one block's range

// ---------------- scratch (device globals; no allocation allowed) ------------
__device__ __align__(16) float g_tmp[N];          // bucket-grouped values
__device__ __align__(16) float g_sorted[N];       // fully sorted
__device__ __align__(16) int   g_cnt[NB];         // INVARIANT: zero at entry; re-zeroed phase 2
__device__ __align__(16) int   g_start[NB + 4];   // bucket starts; [NB] = N
__device__ __align__(16) int   g_coarse[NCOARSE]; // INVARIANT: zero at entry; re-zeroed phase 2
__device__ float g_pmse[GRID], g_pd2[GRID], g_pdens[GRID], g_pdmax[GRID];
__device__ unsigned g_arrive = 0;  // barrier arrival counter (self-resetting)
__device__ unsigned g_epoch  = 0;  // barrier epoch (monotonic, wrap-safe)
__device__ unsigned g_done   = 0;  // finalize counter (self-resetting)

// ---------------- helpers -----------------------------------------------------
__device__ __forceinline__ float warp_sum(float v) {
#pragma unroll
    for (int o = 16; o > 0; o >>= 1) v += __shfl_xor_sync(0xffffffffu, v, o);
    return v;
}
__device__ __forceinline__ float warp_max(float v) {
#pragma unroll
    for (int o = 16; o > 0; o >>= 1) v = fmaxf(v, __shfl_xor_sync(0xffffffffu, v, o));
    return v;
}
__device__ __forceinline__ int warp_sumi(int v) {
#pragma unroll
    for (int o = 16; o > 0; o >>= 1) v += __shfl_xor_sync(0xffffffffu, v, o);
    return v;
}
__device__ __forceinline__ unsigned int okey(float f) {
    unsigned int u = __float_as_uint(f);
    return (u & 0x80000000u) ? ~u : (u | 0x80000000u);
}

// grid-wide flat barrier: all GRID blocks co-resident (GRID=64 < 148 SMs).
// __threadfence orders writes into L2 AND emits CCTL.IVALL (own-L1 invalidate),
// so post-barrier plain loads refetch fresh data from L2.
__device__ __forceinline__ void grid_sync(unsigned base, unsigned ph) {
    __syncthreads();
    if (threadIdx.x == 0) {
        __threadfence();
        unsigned a = atomicAdd(&g_arrive, 1);
        if (a == GRID - 1) {
            atomicExch(&g_arrive, 0);
            __threadfence();
            atomicAdd(&g_epoch, 1);     // release
        } else {
            while ((*(volatile unsigned*)&g_epoch) - base < ph) { }
        }
    }
    __syncthreads();
}

__global__ void __launch_bounds__(TPB, 1)
fused_kernel(const float* __restrict__ x,   const float* __restrict__ tgt,
             const float* __restrict__ w1,  const float* __restrict__ b1,
             const float* __restrict__ w2,  const float* __restrict__ b2,
             float* __restrict__ out) {
    __shared__ float sw1x2[H], sb1x2[H], sw2[H], sc2[H];
    __shared__ float sA[NW], sB[NW];
    __shared__ int   sI[NW];
    __shared__ int   scoarse[NCOARSE];
    __shared__ unsigned s_base;
    __shared__ int   s_final;

    const int tid = threadIdx.x;
    const int blk = blockIdx.x;
    const int gi  = blk * TPB + tid;
    const int lane = tid & 31, wid = tid >> 5;

    if (tid == 0) s_base = *(volatile unsigned*)&g_epoch;  // pre-barrier, uniform

    if (tid < H) {
        float a = w1[tid];
        float c = w2[tid];
        sw1x2[tid] = a + a;            // fold x2 of exp(2u) into weights
        sb1x2[tid] = 2.0f * b1[tid];
        sw2[tid] = c;
        sc2[tid] = -2.0f * c * a * a;  // coeff of t*(1-t^2) in d2y/dx2
    }
    if (tid < NCOARSE) scoarse[tid] = 0;
    __syncthreads();
    const unsigned base = s_base;

    // ---------------- phase 0: MLP partials + fine/coarse histogram -------------
    const float xv = x[gi];
    float pred = b2[0];
    float d2 = 0.0f;
#pragma unroll
    for (int h = 0; h < H; ++h) {
        float u2 = fmaf(xv, sw1x2[h], sb1x2[h]);
        float e  = __expf(u2);
        float t  = 1.0f - __fdividef(2.0f, e + 1.0f);     // tanh(u)
        pred = fmaf(sw2[h], t, pred);
        float t2 = t * t;
        float g  = fmaf(-t2, t, t);                       // t - t^3
        d2 = fmaf(sc2[h], g, d2);
    }
    {
        float err = pred - tgt[gi];
        float vm = warp_sum(err * err);
        float vd = warp_sum(d2 * d2);
        if (lane == 0) { sA[wid] = vm; sB[wid] = vd; }
        __syncthreads();
        if (tid == 0) {
            float m = 0, d = 0;
#pragma unroll
            for (int w = 0; w < NW; ++w) { m += sA[w]; d += sB[w]; }
            g_pmse[blk] = m; g_pd2[blk] = d;
        }
    }
    const unsigned b = okey(xv) >> 16;
    const int r_i = atomicAdd(&g_cnt[b], 1);   // within-bucket index (free slot id)
    atomicAdd(&scoarse[b >> 10], 1);           // coarse histogram in smem
    __syncthreads();
    if (tid < NCOARSE && scoarse[tid]) atomicAdd(&g_coarse[tid], scoarse[tid]);

    grid_sync(base, 1);

    // ---------------- phase 1: scan + absolute bucket starts --------------------
    int4 c4 = reinterpret_cast<const int4*>(g_cnt)[gi];
    int s = c4.x + c4.y + c4.z + c4.w;
    int inc = s;
#pragma unroll
    for (int o = 1; o < 32; o <<= 1) {
        int nb = __shfl_up_sync(0xffffffffu, inc, o);
        if (lane >= o) inc += nb;
    }
    if (lane == 31) sI[wid] = inc;
    __syncthreads();
    if (wid == 0 && lane < NW) {
        int v = sI[lane];
        int wi = v;
#pragma unroll
        for (int o = 1; o < NW; o <<= 1) {
            int nb = __shfl_up_sync((1u << NW) - 1u, wi, o);
            if (lane >= o) wi += nb;
        }
        sI[lane] = wi - v;
    }
    __syncthreads();
    int e_blk = sI[wid] + (inc - s);     // block-local exclusive base
    __syncthreads();                     // sI reuse boundary
    {
        int pv = (tid < blk) ? g_coarse[tid] : 0;  // coarse bin j == block j's range
        pv = warp_sumi(pv);
        if (lane == 0) sI[wid] = pv;
        __syncthreads();
        int bbase = 0;
#pragma unroll
        for (int w = 0; w < NW; ++w) bbase += sI[w];
        int e_abs = bbase + e_blk;
        int4 o4;
        o4.x = e_abs;
        o4.y = o4.x + c4.x;
        o4.z = o4.y + c4.y;
        o4.w = o4.z + c4.z;
        reinterpret_cast<int4*>(g_start)[gi] = o4;
        if (blk == GRID - 1 && tid == TPB - 1) g_start[NB] = e_abs + s;  // = N
    }

    grid_sync(base, 2);

    // ---------------- phase 2: atomic-free scatter + restore invariants ---------
    reinterpret_cast<int4*>(g_cnt)[gi] = make_int4(0, 0, 0, 0);
    if (blk == 0 && tid < NCOARSE) g_coarse[tid] = 0;
    g_tmp[g_start[b] + r_i] = xv;

    grid_sync(base, 3);

    // ---------------- phase 3: rank-in-segment + sorted write -------------------
    {
        float v = g_tmp[gi];
        unsigned kv = okey(v);
        unsigned bb = kv >> 16;
        int st = g_start[bb];
        int en = g_start[bb + 1];
        int r = 0;
        for (int q = st; q < en; ++q) {
            unsigned kq = okey(g_tmp[q]);
            // equal keys are bit-identical floats -> deterministic final contents
            r += (kq < kv) || (kq == kv && q < gi);
        }
        g_sorted[st + r] = v;
    }

    grid_sync(base, 4);

    // ---------------- phase 4: density (coalesced sorted neighbors) -------------
    {
        float xi = g_sorted[gi];
        float c0 = (gi >= 1)     ? xi - g_sorted[gi - 1] : FLT_MAX;
        float c1 = (gi >= 2)     ? xi - g_sorted[gi - 2] : FLT_MAX;
        float c2 = (gi + 1 < N)  ? g_sorted[gi + 1] - xi : FLT_MAX;
        float c3 = (gi + 2 < N)  ? g_sorted[gi + 2] - xi : FLT_MAX;
        float m1 = fminf(c0, c2);
        float m2 = (c0 < c2) ? fminf(c1, c2) : fminf(c0, c3);
        float knn_mean = (m1 + m2 + 3.0f * EPSF) * (1.0f / 3.0f);
        float dens = 1.0f / (knn_mean + EPSF);

        float vs = warp_sum(dens);
        float vx = warp_max(dens);
        if (lane == 0) { sA[wid] = vs; sB[wid] = vx; }
        __syncthreads();
        if (tid == 0) {
            float ds = 0, dx = 0;
#pragma unroll
            for (int w = 0; w < NW; ++w) { ds += sA[w]; dx = fmaxf(dx, sB[w]); }
            g_pdens[blk] = ds; g_pdmax[blk] = dx;
        }
    }

    // ---------------- phase 5: last-arriving block finalizes --------------------
    if (tid == 0) {
        __threadfence();                      // push partials to L2 + IVALL own L1
        unsigned old = atomicAdd(&g_done, 1);
        s_final = (old == GRID - 1);
        if (s_final) atomicExch(&g_done, 0);  // reset invariant
    }
    __syncthreads();
    if (s_final) {
        float vm = (tid < GRID) ? __ldcg(&g_pmse[tid])  : 0.0f;
        float vd = (tid < GRID) ? __ldcg(&g_pd2[tid])   : 0.0f;
        float vs = (tid < GRID) ? __ldcg(&g_pdens[tid]) : 0.0f;
        float vx = (tid < GRID) ? __ldcg(&g_pdmax[tid]) : 0.0f;
        vm = warp_sum(vm);
        vd = warp_sum(vd);
        vs = warp_sum(vs);
        vx = warp_max(vx);
        if (lane == 0) { sA[wid] = vm; sB[wid] = vd; sw1x2[wid] = vs; sw2[wid] = vx; }
        __syncthreads();
        if (tid == 0) {
            float msum = 0, dsum2 = 0, densum = 0, dmax = 0;
#pragma unroll
            for (int w = 0; w < NW; ++w) {
                msum += sA[w]; dsum2 += sB[w];
                densum += sw1x2[w]; dmax = fmaxf(dmax, sw2[w]);
            }
            float mse  = msum * (1.0f / N);
            float md2  = dsum2 * (1.0f / N);
            float mean_dnorm = (densum * (1.0f / N)) / (dmax + EPSF);
            float mean_w = 1.0f + 0.1f * mean_dnorm;
            float penalty = 0.01f * mean_w * md2;
            out[0] = mse + penalty;
            out[1] = mse;
            out[2] = penalty;
        }
    }
}

// ---------------- launch ----------------------------------------------------------
extern "C" void kernel_launch(void* const* d_in, const int* in_sizes, int n_in,
                              void* d_out, int out_size) {
    const float* x   = (const float*)d_in[0];
    const float* tgt = (const float*)d_in[1];
    const float* w1  = (const float*)d_in[2];
    const float* b1  = (const float*)d_in[3];
    const float* w2  = (const float*)d_in[4];
    const float* b2  = (const float*)d_in[5];
    float* out = (float*)d_out;

    fused_kernel<<<GRID, TPB>>>(x, tgt, w1, b1, w2, b2, out);
    (void)in_sizes; (void)n_in; (void)out_size;
}